// round 12
// baseline (speedup 1.0000x reference)
#include <cuda_runtime.h>
#include <cuda_bf16.h>
#include <math.h>
#include <stdint.h>

#define N 6144
#define D 128
#define INV_TAU 10.0f
#define NB (2 * N)
#define GMAX 128
#define NT 64        // j-tiles (32 wide) per block chunk: 64*32 = 2048
#define TJ 32        // tile width in j

// ---------------- device scratch ----------------
__device__ __nv_bfloat16 g_Abf[N * D];
__device__ __nv_bfloat16 g_Bbf[NB * D];
__device__ float g_repr[2][N * D];
__device__ float g_rowsum[2][N];
__device__ float g_pos[2][N];
__device__ float g_sumall[2][N];
__device__ float g_weights[N * 2];
__device__ float g_loss_acc;
__device__ int   g_cnt[2][N];
__device__ int   g_lidx[2][N][GMAX];

// ---------------- PTX helpers ----------------
__device__ __forceinline__ uint32_t s2u(const void* p) {
    uint32_t a;
    asm("{ .reg .u64 t; cvta.to.shared.u64 t, %1; cvt.u32.u64 %0, t; }" : "=r"(a) : "l"(p));
    return a;
}
__device__ __forceinline__ void cp16(uint32_t dst, const void* src) {
    asm volatile("cp.async.cg.shared.global [%0], [%1], 16;" :: "r"(dst), "l"(src));
}
#define CP_COMMIT() asm volatile("cp.async.commit_group;")
__device__ __forceinline__ void ldsm4(uint32_t* r, uint32_t addr) {
    asm volatile("ldmatrix.sync.aligned.m8n8.x4.shared.b16 {%0,%1,%2,%3}, [%4];"
                 : "=r"(r[0]), "=r"(r[1]), "=r"(r[2]), "=r"(r[3]) : "r"(addr));
}
__device__ __forceinline__ void mma_bf16(float* d, const uint32_t* a, uint32_t b0, uint32_t b1) {
    asm volatile(
        "mma.sync.aligned.m16n8k16.row.col.f32.bf16.bf16.f32 "
        "{%0,%1,%2,%3}, {%4,%5,%6,%7}, {%8,%9}, {%0,%1,%2,%3};"
        : "+f"(d[0]), "+f"(d[1]), "+f"(d[2]), "+f"(d[3])
        : "r"(a[0]), "r"(a[1]), "r"(a[2]), "r"(a[3]), "r"(b0), "r"(b1));
}

// SMEM layout: A tile 128x(128+8pad) bf16; simB double-buffered 32x(128+8) bf16;
// adj triple-buffered 128x(32+4pad) fp32.
#define ASTRIDE 272
#define BSTRIDE 272
#define BTILE 8704            // 32 * 272
#define ADJSTRIDE 144         // bytes = 36 floats
#define ADJTILE 18432         // 128 * 144
static constexpr int OFF_A = 0;
static constexpr int OFF_B = 34816;
static constexpr int OFF_ADJ = OFF_B + 2 * BTILE;              // 52224
static constexpr int FUSED_SMEM = OFF_ADJ + 3 * ADJTILE;       // 107520

// ---------------- K0: zero ----------------
__global__ void k_zero() {
    int idx = blockIdx.x * blockDim.x + threadIdx.x;
    if (idx < 2 * N) {
        int a = idx / N, b = idx % N;
        g_sumall[a][b] = 0.0f;
        g_pos[a][b] = 0.0f;
        g_rowsum[a][b] = 0.0f;
        g_cnt[a][b] = 0;
    }
    if (idx == 0) g_loss_acc = 0.0f;
}

// ---------------- K1: normalize -> bf16 only ----------------
__global__ void k_normalize(const float* __restrict__ embF,
                            const float* __restrict__ embM,
                            const float* __restrict__ embP) {
    int i = blockIdx.x;
    int which = blockIdx.y;
    const float* src = (which == 0) ? embF : (which == 1) ? embM : embP;
    int t = threadIdx.x;  // 128
    float v = src[(size_t)i * D + t];
    __shared__ float red[128];
    red[t] = v * v;
    __syncthreads();
#pragma unroll
    for (int s = 64; s > 0; s >>= 1) {
        if (t < s) red[t] += red[t + s];
        __syncthreads();
    }
    float norm = fmaxf(sqrtf(red[0]), 1e-12f);
    __nv_bfloat16 h = __float2bfloat16(v / norm);
    if (which == 0) g_Abf[i * D + t] = h;
    else g_Bbf[((which == 1) ? i : (N + i)) * D + t] = h;
}

// ---------------- K2: FUSED sim GEMM + adjacency stream ----------------
__global__ __launch_bounds__(256, 2) void k_fused(const float* __restrict__ FM_adj,
                                                  const float* __restrict__ FP_adj) {
    extern __shared__ __align__(16) char dsm[];
    const uint32_t smb = s2u(dsm);
    const int tid = threadIdx.x;
    const int wid = tid >> 5;
    const int lane = tid & 31;
    const int wm = (wid & 3) * 32;
    const int wn = (wid >> 2) * 16;
    const int i0 = blockIdx.x * 128;
    const int by = blockIdx.y;           // 0..5
    const int w = (by >= 3) ? 1 : 0;
    const int jg0 = by * 2048;           // into g_Bbf
    const int jl0 = jg0 - w * N;         // into adj matrix (local cols)
    const float* adjm = w ? FP_adj : FM_adj;

    const uint32_t aoff = (uint32_t)(lane & 15) * ASTRIDE + (uint32_t)(lane >> 4) * 16;
    const uint32_t boff = (uint32_t)(((lane >> 3) & 1) * 8 + (lane & 7)) * BSTRIDE
                        + (uint32_t)(lane >> 4) * 16;

    // A tile (once): 128 rows x 16 chunks = 2048
#pragma unroll
    for (int p = 0; p < 8; ++p) {
        int idx = tid + (p << 8);
        int r = idx >> 4, c = idx & 15;
        cp16(smb + OFF_A + r * ASTRIDE + c * 16, &g_Abf[(size_t)(i0 + r) * D + c * 8]);
    }

    // tile loader: simB 32 rows x 16 chunks = 512; adj 128 rows x 8 chunks = 1024
    auto issue_tile = [&](int t) {
        int jb = jg0 + t * TJ;
        int jl = jl0 + t * TJ;
        uint32_t bbuf = smb + OFF_B + (t & 1) * BTILE;
        uint32_t abuf = smb + OFF_ADJ + (t % 3) * ADJTILE;
#pragma unroll
        for (int p = 0; p < 2; ++p) {
            int idx = tid + (p << 8);
            int r = idx >> 4, c = idx & 15;   // FIX: full 128-col rows (16 chunks)
            cp16(bbuf + r * BSTRIDE + c * 16, &g_Bbf[(size_t)(jb + r) * D + c * 8]);
        }
#pragma unroll
        for (int p = 0; p < 4; ++p) {
            int idx = tid + (p << 8);
            int r = idx >> 3, c = idx & 7;
            cp16(abuf + r * ADJSTRIDE + c * 16, adjm + (size_t)(i0 + r) * N + jl + c * 4);
        }
    };

    issue_tile(0);
    CP_COMMIT();   // group 0: A + tile0
    issue_tile(1);
    CP_COMMIT();   // group 1: tile1

    float rsum[2][2] = {{0, 0}, {0, 0}};
    float posr[2][2] = {{0, 0}, {0, 0}};
    float radj[2][2] = {{0, 0}, {0, 0}};

    for (int t = 0; t < NT; ++t) {
        asm volatile("cp.async.wait_group 1;");
        __syncthreads();

        const uint32_t bb = smb + OFF_B + (t & 1) * BTILE;
        const float* adjf = (const float*)(dsm + OFF_ADJ + (t % 3) * ADJTILE);

        float acc[2][2][4];
#pragma unroll
        for (int f = 0; f < 2; ++f)
#pragma unroll
            for (int n = 0; n < 2; ++n)
#pragma unroll
                for (int r = 0; r < 4; ++r) acc[f][n][r] = 0.0f;

#pragma unroll
        for (int ks = 0; ks < 8; ++ks) {
            uint32_t ah[2][4];
#pragma unroll
            for (int f = 0; f < 2; ++f)
                ldsm4(ah[f], smb + OFF_A + (wm + f * 16) * ASTRIDE + ks * 32 + aoff);
            uint32_t bh[4];
            ldsm4(bh, bb + wn * BSTRIDE + ks * 32 + boff);
#pragma unroll
            for (int f = 0; f < 2; ++f) {
                mma_bf16(acc[f][0], ah[f], bh[0], bh[2]);
                mma_bf16(acc[f][1], ah[f], bh[1], bh[3]);
            }
        }

        __syncthreads();
        if (t + 2 < NT) issue_tile(t + 2);
        CP_COMMIT();

        // epilogue: exp rowsum + adj-masked pos + rowsum + list append
        const int jbase = jl0 + t * TJ;
#pragma unroll
        for (int f = 0; f < 2; ++f)
#pragma unroll
            for (int n = 0; n < 2; ++n)
#pragma unroll
                for (int r = 0; r < 4; ++r) {
                    int row = wm + f * 16 + (lane >> 2) + (r >> 1) * 8;
                    int col = wn + n * 8 + (lane & 3) * 2 + (r & 1);
                    float e = __expf(acc[f][n][r] * INV_TAU);
                    rsum[f][r >> 1] += e;
                    float a = adjf[row * 36 + col];
                    if (a != 0.0f) {
                        posr[f][r >> 1] += e;
                        radj[f][r >> 1] += 1.0f;
                        int p = atomicAdd(&g_cnt[w][i0 + row], 1);
                        if (p < GMAX) g_lidx[w][i0 + row][p] = jbase + col;
                    }
                }
    }

    // reduce over the 4 lanes sharing a row, then global atomics
#pragma unroll
    for (int f = 0; f < 2; ++f)
#pragma unroll
        for (int h = 0; h < 2; ++h) {
            float s = rsum[f][h], p = posr[f][h], a = radj[f][h];
#pragma unroll
            for (int o = 1; o <= 2; o <<= 1) {
                s += __shfl_xor_sync(0xffffffffu, s, o);
                p += __shfl_xor_sync(0xffffffffu, p, o);
                a += __shfl_xor_sync(0xffffffffu, a, o);
            }
            if ((lane & 3) == 0) {
                int row = i0 + wm + f * 16 + (lane >> 2) + h * 8;
                atomicAdd(&g_sumall[w][row], s);
                atomicAdd(&g_pos[w][row], p);
                atomicAdd(&g_rowsum[w][row], a);
            }
        }
}

// ---------------- K3: gather repr from lists (exact fp32) ----------------
__global__ __launch_bounds__(128) void k_gather(const float* __restrict__ embM,
                                                const float* __restrict__ embP) {
    const int i = blockIdx.x;
    const int w = blockIdx.y;
    const float* emb = (w == 0) ? embM : embP;
    const int t = threadIdx.x;

    __shared__ int s_idx[GMAX];

    const int cnt = min(g_cnt[w][i], GMAX);
    if (t < cnt) s_idx[t] = g_lidx[w][i][t];
    __syncthreads();

    const float denom = fmaxf(g_rowsum[w][i], 1.0f);

    float a0 = 0, a1 = 0, a2 = 0, a3 = 0;
    int e = 0;
    for (; e + 4 <= cnt; e += 4) {
        a0 += emb[(size_t)s_idx[e + 0] * D + t];
        a1 += emb[(size_t)s_idx[e + 1] * D + t];
        a2 += emb[(size_t)s_idx[e + 2] * D + t];
        a3 += emb[(size_t)s_idx[e + 3] * D + t];
    }
    for (; e < cnt; ++e) a0 += emb[(size_t)s_idx[e] * D + t];
    g_repr[w][(size_t)i * D + t] = ((a0 + a1) + (a2 + a3)) / denom;
}

// ---------------- K4: MLP + softmax ----------------
#define MLP_ROWS 16
#define FSTR 257
#define MLP_SMEM ((MLP_ROWS * FSTR) * (int)sizeof(float))
__global__ __launch_bounds__(256) void k_mlp(const float* __restrict__ W1,
                                             const float* __restrict__ b1,
                                             const float* __restrict__ W2,
                                             const float* __restrict__ b2,
                                             float* __restrict__ out_weights) {
    extern __shared__ float feats[];

    const int tid = threadIdx.x;
    const int lane = tid & 31;
    const int wp = tid >> 5;
    const int i0 = blockIdx.x * MLP_ROWS;

#pragma unroll
    for (int p = 0; p < MLP_ROWS; ++p) {
        int s = tid + p * 256;
        int r = s >> 8, k = s & 255;
        feats[r * FSTR + k] = (k < 128) ? g_repr[0][(size_t)(i0 + r) * D + k]
                                        : g_repr[1][(size_t)(i0 + r) * D + (k - 128)];
    }
    __syncthreads();

    const int c4 = lane;
    const float4* W1v = (const float4*)W1;
    const float4 b1v = ((const float4*)b1)[c4];
    const float4 w2a = ((const float4*)W2)[2 * c4];
    const float4 w2b = ((const float4*)W2)[2 * c4 + 1];
    const int r0 = wp * 2;

    float acc[2][4];
#pragma unroll
    for (int r = 0; r < 2; ++r)
#pragma unroll
        for (int q = 0; q < 4; ++q) acc[r][q] = 0.0f;

    float4 wv = __ldg(&W1v[c4]);
#pragma unroll 4
    for (int k = 0; k < 256; ++k) {
        float4 nv;
        if (k < 255) nv = __ldg(&W1v[(k + 1) * 32 + c4]);
#pragma unroll
        for (int r = 0; r < 2; ++r) {
            float f = feats[(r0 + r) * FSTR + k];
            acc[r][0] = fmaf(f, wv.x, acc[r][0]);
            acc[r][1] = fmaf(f, wv.y, acc[r][1]);
            acc[r][2] = fmaf(f, wv.z, acc[r][2]);
            acc[r][3] = fmaf(f, wv.w, acc[r][3]);
        }
        wv = nv;
    }

#pragma unroll
    for (int r = 0; r < 2; ++r) {
        float h0 = fmaxf(acc[r][0] + b1v.x, 0.0f);
        float h1 = fmaxf(acc[r][1] + b1v.y, 0.0f);
        float h2 = fmaxf(acc[r][2] + b1v.z, 0.0f);
        float h3 = fmaxf(acc[r][3] + b1v.w, 0.0f);
        float p0 = h0 * w2a.x + h1 * w2a.z + h2 * w2b.x + h3 * w2b.z;
        float p1 = h0 * w2a.y + h1 * w2a.w + h2 * w2b.y + h3 * w2b.w;
#pragma unroll
        for (int o = 16; o; o >>= 1) {
            p0 += __shfl_xor_sync(0xffffffffu, p0, o);
            p1 += __shfl_xor_sync(0xffffffffu, p1, o);
        }
        if (lane == 0) {
            int row = i0 + r0 + r;
            float o0 = p0 + b2[0];
            float o1 = p1 + b2[1];
            float mx = fmaxf(o0, o1);
            float e0 = expf(o0 - mx), e1 = expf(o1 - mx);
            float inv = 1.0f / (e0 + e1);
            float w0 = e0 * inv, w1 = e1 * inv;
            g_weights[2 * row] = w0;
            g_weights[2 * row + 1] = w1;
            out_weights[2 * row] = w0;
            out_weights[2 * row + 1] = w1;
        }
    }
}

// ---------------- K5: loss ----------------
__global__ __launch_bounds__(256) void k_loss() {
    int idx = blockIdx.x * blockDim.x + threadIdx.x;
    int stride = gridDim.x * blockDim.x;
    float term = 0.0f;
    for (int i = idx; i < N; i += stride) {
        float w0 = g_weights[2 * i], w1 = g_weights[2 * i + 1];
        float pm = g_pos[0][i], pp = g_pos[1][i];
        float sm = g_sumall[0][i], sp = g_sumall[1][i];
        float wpv = w0 * pm + w1 * pp;
        float wn = w0 * (sm - pm) + w1 * (sp - pp);
        float nei = fmaxf(g_rowsum[0][i] + g_rowsum[1][i], 1.0f);
        float ratio = wpv / (wpv + wn) / nei;
        ratio = fmaxf(ratio, 1e-10f);
        term += -logf(ratio);
    }
    __shared__ float red[256];
    red[threadIdx.x] = term;
    __syncthreads();
#pragma unroll
    for (int s = 128; s > 0; s >>= 1) {
        if (threadIdx.x < s) red[threadIdx.x] += red[threadIdx.x + s];
        __syncthreads();
    }
    if (threadIdx.x == 0) atomicAdd(&g_loss_acc, red[0]);
}

__global__ void k_finalize(float* __restrict__ out) {
    out[0] = g_loss_acc / (float)N;
}

// ---------------- launch (single stream; fusion replaces overlap tricks) ----
extern "C" void kernel_launch(void* const* d_in, const int* in_sizes, int n_in,
                              void* d_out, int out_size) {
    const float* embF = (const float*)d_in[0];
    const float* embM = (const float*)d_in[1];
    const float* embP = (const float*)d_in[2];
    const float* FM_adj = (const float*)d_in[3];
    const float* FP_adj = (const float*)d_in[4];
    const float* W1 = (const float*)d_in[5];
    const float* b1 = (const float*)d_in[6];
    const float* W2 = (const float*)d_in[7];
    const float* b2 = (const float*)d_in[8];
    float* out = (float*)d_out;

    static bool attr_set = false;
    if (!attr_set) {
        cudaFuncSetAttribute(k_fused, cudaFuncAttributeMaxDynamicSharedMemorySize, FUSED_SMEM);
        cudaFuncSetAttribute(k_mlp, cudaFuncAttributeMaxDynamicSharedMemorySize, MLP_SMEM);
        attr_set = true;
    }

    k_zero<<<(2 * N + 255) / 256, 256>>>();
    k_normalize<<<dim3(N, 3), 128>>>(embF, embM, embP);
    k_fused<<<dim3(N / 128, 6), 256, FUSED_SMEM>>>(FM_adj, FP_adj);
    k_gather<<<dim3(N, 2), 128>>>(embM, embP);
    k_mlp<<<N / MLP_ROWS, 256, MLP_SMEM>>>(W1, b1, W2, b2, out + 1);
    k_loss<<<24, 256>>>();
    k_finalize<<<1, 1>>>(out);
}

// round 13
// speedup vs baseline: 1.8730x; 1.8730x over previous
#include <cuda_runtime.h>
#include <cuda_bf16.h>
#include <math.h>
#include <stdint.h>

#define N 6144
#define D 128
#define INV_TAU 10.0f
#define NB (2 * N)
#define JSPLIT 12
#define TILES_PER 16   // 12*16*64 = 12288 columns

// ---------------- device scratch ----------------
__device__ float g_Fn[N * D];
__device__ float g_Mn[N * D];
__device__ float g_Pn[N * D];
__device__ __nv_bfloat16 g_Abf[N * D];
__device__ __nv_bfloat16 g_Bbf[NB * D];
__device__ float g_repr[2][N * D];
__device__ float g_rowsum[2][N];
__device__ float g_pos[2][N];
__device__ float g_sumall[2][N];
__device__ float g_weights[N * 2];
__device__ float g_loss_acc;

// ---------------- PTX helpers ----------------
__device__ __forceinline__ uint32_t s2u(const void* p) {
    uint32_t a;
    asm("{ .reg .u64 t; cvta.to.shared.u64 t, %1; cvt.u32.u64 %0, t; }" : "=r"(a) : "l"(p));
    return a;
}
__device__ __forceinline__ void cp16(uint32_t dst, const void* src) {
    asm volatile("cp.async.cg.shared.global [%0], [%1], 16;" :: "r"(dst), "l"(src));
}
#define CP_COMMIT() asm volatile("cp.async.commit_group;")
__device__ __forceinline__ void ldsm4(uint32_t* r, uint32_t addr) {
    asm volatile("ldmatrix.sync.aligned.m8n8.x4.shared.b16 {%0,%1,%2,%3}, [%4];"
                 : "=r"(r[0]), "=r"(r[1]), "=r"(r[2]), "=r"(r[3]) : "r"(addr));
}
__device__ __forceinline__ void mma_bf16(float* d, const uint32_t* a, uint32_t b0, uint32_t b1) {
    asm volatile(
        "mma.sync.aligned.m16n8k16.row.col.f32.bf16.bf16.f32 "
        "{%0,%1,%2,%3}, {%4,%5,%6,%7}, {%8,%9}, {%0,%1,%2,%3};"
        : "+f"(d[0]), "+f"(d[1]), "+f"(d[2]), "+f"(d[3])
        : "r"(a[0]), "r"(a[1]), "r"(a[2]), "r"(a[3]), "r"(b0), "r"(b1));
}

// SMEM tiles (stride 272 B = 128 data + 16 pad -> conflict-free ldmatrix)
#define TSTRIDE 272
#define A_TILE_BYTES (128 * TSTRIDE)   // 34816
#define B_TILE_BYTES (64 * TSTRIDE)    // 17408
static constexpr int OFF_A = 0;
static constexpr int OFF_B = A_TILE_BYTES;
static constexpr int SIMTC_SMEM = A_TILE_BYTES + 2 * B_TILE_BYTES;  // 69632

// ---------------- K0: zero ----------------
__global__ void k_zero() {
    int idx = blockIdx.x * blockDim.x + threadIdx.x;
    if (idx < 2 * N) g_sumall[idx / N][idx % N] = 0.0f;
    if (idx == 0) g_loss_acc = 0.0f;
}

// ---------------- K1: normalize + bf16 cast ----------------
__global__ void k_normalize(const float* __restrict__ embF,
                            const float* __restrict__ embM,
                            const float* __restrict__ embP) {
    int i = blockIdx.x;
    int which = blockIdx.y;
    const float* src = (which == 0) ? embF : (which == 1) ? embM : embP;
    float* dst = (which == 0) ? g_Fn : (which == 1) ? g_Mn : g_Pn;
    int t = threadIdx.x;  // 128
    float v = src[(size_t)i * D + t];
    __shared__ float red[128];
    red[t] = v * v;
    __syncthreads();
#pragma unroll
    for (int s = 64; s > 0; s >>= 1) {
        if (t < s) red[t] += red[t + s];
        __syncthreads();
    }
    float norm = fmaxf(sqrtf(red[0]), 1e-12f);
    float nv = v / norm;
    dst[(size_t)i * D + t] = nv;
    __nv_bfloat16 h = __float2bfloat16(nv);
    if (which == 0) g_Abf[i * D + t] = h;
    else g_Bbf[((which == 1) ? i : (N + i)) * D + t] = h;
}

// ---------------- K2: adjacency scan (lean hot path, no ballots) ----------------
// adj values are non-negative; per float4 one unconditional sum + one branch.
// Rare hit path (~2% of float4s): one shared atomic + direct writes.
#define MAXNZ 768
__global__ __launch_bounds__(128) void k_repr_pos(
    const float* __restrict__ FM_adj, const float* __restrict__ FP_adj,
    const float* __restrict__ embM, const float* __restrict__ embP) {
    int i = blockIdx.x;
    int w = blockIdx.y;
    const float* adj = (w == 0) ? FM_adj : FP_adj;
    const float* emb = (w == 0) ? embM : embP;
    const float* nrm = (w == 0) ? g_Mn : g_Pn;
    int t = threadIdx.x;
    int lane = t & 31;

    __shared__ int s_idx[MAXNZ];
    __shared__ float s_val[MAXNZ];
    __shared__ int s_cnt;
    __shared__ float s_rowsum;
    __shared__ float s_pos;
    __shared__ float s_F[D];

    if (t == 0) { s_cnt = 0; s_rowsum = 0.0f; s_pos = 0.0f; }
    s_F[t] = g_Fn[(size_t)i * D + t];
    __syncthreads();

    const float4* arow = (const float4*)(adj + (size_t)i * N);
    float myrs = 0.0f;
#pragma unroll 4
    for (int c = t; c < N / 4; c += 128) {
        float4 v = __ldcs(&arow[c]);
        float s = (v.x + v.y) + (v.z + v.w);
        myrs += s;
        if (s != 0.0f) {  // rare (~2%)
            int nh = (v.x != 0.0f) + (v.y != 0.0f) + (v.z != 0.0f) + (v.w != 0.0f);
            int p = atomicAdd(&s_cnt, nh);
            if (v.x != 0.0f) { if (p < MAXNZ) { s_idx[p] = 4 * c + 0; s_val[p] = v.x; } ++p; }
            if (v.y != 0.0f) { if (p < MAXNZ) { s_idx[p] = 4 * c + 1; s_val[p] = v.y; } ++p; }
            if (v.z != 0.0f) { if (p < MAXNZ) { s_idx[p] = 4 * c + 2; s_val[p] = v.z; } ++p; }
            if (v.w != 0.0f) { if (p < MAXNZ) { s_idx[p] = 4 * c + 3; s_val[p] = v.w; } ++p; }
        }
    }
#pragma unroll
    for (int o = 16; o; o >>= 1) myrs += __shfl_xor_sync(0xffffffffu, myrs, o);
    if (lane == 0) atomicAdd(&s_rowsum, myrs);
    __syncthreads();

    int cnt = min(s_cnt, MAXNZ);
    float rs = s_rowsum;
    float denom = fmaxf(rs, 1.0f);

    // repr gather: thread t = dim, 4 accumulation chains
    float a0 = 0, a1 = 0, a2 = 0, a3 = 0;
    int e = 0;
    for (; e + 4 <= cnt; e += 4) {
        a0 += s_val[e + 0] * emb[(size_t)s_idx[e + 0] * D + t];
        a1 += s_val[e + 1] * emb[(size_t)s_idx[e + 1] * D + t];
        a2 += s_val[e + 2] * emb[(size_t)s_idx[e + 2] * D + t];
        a3 += s_val[e + 3] * emb[(size_t)s_idx[e + 3] * D + t];
    }
    for (; e < cnt; ++e) a0 += s_val[e] * emb[(size_t)s_idx[e] * D + t];
    g_repr[w][(size_t)i * D + t] = ((a0 + a1) + (a2 + a3)) / denom;
    if (t == 0) g_rowsum[w][i] = rs;

    // pos: warp-per-entry dot products
    int warp = t >> 5;
    float lp = 0.0f;
    for (int q = warp; q < cnt; q += 4) {
        int j = s_idx[q];
        const float* nr = nrm + (size_t)j * D;
        float pd = s_F[lane] * nr[lane]
                 + s_F[lane + 32] * nr[lane + 32]
                 + s_F[lane + 64] * nr[lane + 64]
                 + s_F[lane + 96] * nr[lane + 96];
#pragma unroll
        for (int o = 16; o; o >>= 1) pd += __shfl_xor_sync(0xffffffffu, pd, o);
        if (lane == 0) lp += s_val[q] * __expf(pd * INV_TAU);
    }
    if (lane == 0) atomicAdd(&s_pos, lp);
    __syncthreads();
    if (t == 0) g_pos[w][i] = s_pos;
}

// ---------------- K3: bf16 HMMA sim row sums (BN=64) ----------------
__device__ __forceinline__ void load_tileA(uint32_t dst, const __nv_bfloat16* src,
                                           int row0, int tid) {
#pragma unroll
    for (int p = 0; p < 8; ++p) {
        int idx = tid + (p << 8);
        int r = idx >> 4, c = idx & 15;
        cp16(dst + r * TSTRIDE + c * 16, src + (size_t)(row0 + r) * D + c * 8);
    }
}
__device__ __forceinline__ void load_tileB(uint32_t dst, const __nv_bfloat16* src,
                                           int row0, int tid) {
#pragma unroll
    for (int p = 0; p < 4; ++p) {
        int idx = tid + (p << 8);
        int r = idx >> 4, c = idx & 15;
        cp16(dst + r * TSTRIDE + c * 16, src + (size_t)(row0 + r) * D + c * 8);
    }
}

__global__ __launch_bounds__(256, 2) void k_simsum_mma() {
    extern __shared__ __align__(16) char dsm[];
    const uint32_t smb = s2u(dsm);
    const int tid = threadIdx.x;
    const int wid = tid >> 5;
    const int lane = tid & 31;
    const int wm = (wid & 3) * 32;
    const int wn = (wid >> 2) * 32;
    const int i0 = blockIdx.x * 128;
    const int tbase = blockIdx.y * TILES_PER;
    const int tgt = (blockIdx.y < JSPLIT / 2) ? 0 : 1;

    const uint32_t aoff = (uint32_t)(lane & 15) * TSTRIDE + (uint32_t)(lane >> 4) * 16;
    const uint32_t boff = (uint32_t)(((lane >> 3) & 1) * 8 + (lane & 7)) * TSTRIDE
                        + (uint32_t)(lane >> 4) * 16;

    load_tileA(smb + OFF_A, g_Abf, i0, tid);
    load_tileB(smb + OFF_B, g_Bbf, tbase * 64, tid);
    CP_COMMIT();
    load_tileB(smb + OFF_B + B_TILE_BYTES, g_Bbf, (tbase + 1) * 64, tid);
    CP_COMMIT();

    float rsum[2][2] = {{0, 0}, {0, 0}};

    for (int t = 0; t < TILES_PER; ++t) {
        const int buf = t & 1;
        asm volatile("cp.async.wait_group 1;");
        __syncthreads();

        const uint32_t bb = smb + OFF_B + buf * B_TILE_BYTES;

        float acc[2][4][4];
#pragma unroll
        for (int f = 0; f < 2; ++f)
#pragma unroll
            for (int n = 0; n < 4; ++n)
#pragma unroll
                for (int r = 0; r < 4; ++r) acc[f][n][r] = 0.0f;

#pragma unroll
        for (int ks = 0; ks < 8; ++ks) {
            uint32_t ah[2][4];
#pragma unroll
            for (int f = 0; f < 2; ++f)
                ldsm4(ah[f], smb + OFF_A + (wm + f * 16) * TSTRIDE + ks * 32 + aoff);
#pragma unroll
            for (int g = 0; g < 2; ++g) {
                uint32_t bh[4];
                ldsm4(bh, bb + (wn + g * 16) * TSTRIDE + ks * 32 + boff);
#pragma unroll
                for (int f = 0; f < 2; ++f) {
                    mma_bf16(acc[f][2 * g], ah[f], bh[0], bh[2]);
                    mma_bf16(acc[f][2 * g + 1], ah[f], bh[1], bh[3]);
                }
            }
        }

        __syncthreads();
        if (t + 2 < TILES_PER)
            load_tileB(smb + OFF_B + buf * B_TILE_BYTES, g_Bbf, (tbase + t + 2) * 64, tid);
        CP_COMMIT();

#pragma unroll
        for (int f = 0; f < 2; ++f) {
            float e0 = 0.0f, e1 = 0.0f;
#pragma unroll
            for (int n = 0; n < 4; ++n) {
                e0 += __expf(acc[f][n][0] * INV_TAU) + __expf(acc[f][n][1] * INV_TAU);
                e1 += __expf(acc[f][n][2] * INV_TAU) + __expf(acc[f][n][3] * INV_TAU);
            }
            rsum[f][0] += e0;
            rsum[f][1] += e1;
        }
    }

#pragma unroll
    for (int f = 0; f < 2; ++f)
#pragma unroll
        for (int r = 0; r < 2; ++r) {
            float v = rsum[f][r];
            v += __shfl_xor_sync(0xffffffffu, v, 1);
            v += __shfl_xor_sync(0xffffffffu, v, 2);
            if ((lane & 3) == 0) {
                int row = i0 + wm + f * 16 + (lane >> 2) + r * 8;
                atomicAdd(&g_sumall[tgt][row], v);
            }
        }
}

// ---------------- K4: MLP + softmax (warp-owned rows) ----------------
#define MLP_ROWS 48
#define FSTR 257
#define MLP_SMEM ((256 * 128 + MLP_ROWS * FSTR) * (int)sizeof(float))
__global__ __launch_bounds__(256) void k_mlp(const float* __restrict__ W1,
                                             const float* __restrict__ b1,
                                             const float* __restrict__ W2,
                                             const float* __restrict__ b2,
                                             float* __restrict__ out_weights) {
    extern __shared__ float smf[];
    float* W1s = smf;
    float* feats = smf + 256 * 128;

    const int tid = threadIdx.x;
    const int lane = tid & 31;
    const int wp = tid >> 5;
    const int i0 = blockIdx.x * MLP_ROWS;

#pragma unroll
    for (int p = 0; p < 32; ++p) {
        int s = tid + p * 256;
        ((float4*)W1s)[s] = ((const float4*)W1)[s];
    }
#pragma unroll
    for (int p = 0; p < MLP_ROWS; ++p) {
        int s = tid + p * 256;
        int r = s >> 8, k = s & 255;
        feats[r * FSTR + k] = (k < 128) ? g_repr[0][(size_t)(i0 + r) * D + k]
                                        : g_repr[1][(size_t)(i0 + r) * D + (k - 128)];
    }
    __syncthreads();

    const int c4 = lane;
    const float4 b1v = ((const float4*)b1)[c4];
    const float4 w2a = ((const float4*)W2)[2 * c4];
    const float4 w2b = ((const float4*)W2)[2 * c4 + 1];
    const int r0 = wp * 6;

    float acc[6][4];
#pragma unroll
    for (int r = 0; r < 6; ++r)
#pragma unroll
        for (int q = 0; q < 4; ++q) acc[r][q] = 0.0f;

#pragma unroll 4
    for (int k = 0; k < 256; ++k) {
        float4 wv = *(const float4*)&W1s[k * 128 + 4 * c4];
#pragma unroll
        for (int r = 0; r < 6; ++r) {
            float f = feats[(r0 + r) * FSTR + k];
            acc[r][0] = fmaf(f, wv.x, acc[r][0]);
            acc[r][1] = fmaf(f, wv.y, acc[r][1]);
            acc[r][2] = fmaf(f, wv.z, acc[r][2]);
            acc[r][3] = fmaf(f, wv.w, acc[r][3]);
        }
    }

#pragma unroll
    for (int r = 0; r < 6; ++r) {
        float h0 = fmaxf(acc[r][0] + b1v.x, 0.0f);
        float h1 = fmaxf(acc[r][1] + b1v.y, 0.0f);
        float h2 = fmaxf(acc[r][2] + b1v.z, 0.0f);
        float h3 = fmaxf(acc[r][3] + b1v.w, 0.0f);
        float p0 = h0 * w2a.x + h1 * w2a.z + h2 * w2b.x + h3 * w2b.z;
        float p1 = h0 * w2a.y + h1 * w2a.w + h2 * w2b.y + h3 * w2b.w;
#pragma unroll
        for (int o = 16; o; o >>= 1) {
            p0 += __shfl_xor_sync(0xffffffffu, p0, o);
            p1 += __shfl_xor_sync(0xffffffffu, p1, o);
        }
        if (lane == 0) {
            int row = i0 + r0 + r;
            float o0 = p0 + b2[0];
            float o1 = p1 + b2[1];
            float mx = fmaxf(o0, o1);
            float e0 = expf(o0 - mx), e1 = expf(o1 - mx);
            float inv = 1.0f / (e0 + e1);
            float w0 = e0 * inv, w1 = e1 * inv;
            g_weights[2 * row] = w0;
            g_weights[2 * row + 1] = w1;
            out_weights[2 * row] = w0;
            out_weights[2 * row + 1] = w1;
        }
    }
}

// ---------------- K5: loss ----------------
__global__ __launch_bounds__(256) void k_loss() {
    int idx = blockIdx.x * blockDim.x + threadIdx.x;
    int stride = gridDim.x * blockDim.x;
    float term = 0.0f;
    for (int i = idx; i < N; i += stride) {
        float w0 = g_weights[2 * i], w1 = g_weights[2 * i + 1];
        float pm = g_pos[0][i], pp = g_pos[1][i];
        float sm = g_sumall[0][i], sp = g_sumall[1][i];
        float wpv = w0 * pm + w1 * pp;
        float wn = w0 * (sm - pm) + w1 * (sp - pp);
        float nei = fmaxf(g_rowsum[0][i] + g_rowsum[1][i], 1.0f);
        float ratio = wpv / (wpv + wn) / nei;
        ratio = fmaxf(ratio, 1e-10f);
        term += -logf(ratio);
    }
    __shared__ float red[256];
    red[threadIdx.x] = term;
    __syncthreads();
#pragma unroll
    for (int s = 128; s > 0; s >>= 1) {
        if (threadIdx.x < s) red[threadIdx.x] += red[threadIdx.x + s];
        __syncthreads();
    }
    if (threadIdx.x == 0) atomicAdd(&g_loss_acc, red[0]);
}

__global__ void k_finalize(float* __restrict__ out) {
    out[0] = g_loss_acc / (float)N;
}

// ---------------- launch (fork-join overlap, R8 topology) ----------------
extern "C" void kernel_launch(void* const* d_in, const int* in_sizes, int n_in,
                              void* d_out, int out_size) {
    const float* embF = (const float*)d_in[0];
    const float* embM = (const float*)d_in[1];
    const float* embP = (const float*)d_in[2];
    const float* FM_adj = (const float*)d_in[3];
    const float* FP_adj = (const float*)d_in[4];
    const float* W1 = (const float*)d_in[5];
    const float* b1 = (const float*)d_in[6];
    const float* W2 = (const float*)d_in[7];
    const float* b2 = (const float*)d_in[8];
    float* out = (float*)d_out;

    static cudaStream_t s1 = nullptr;
    static cudaEvent_t evA = nullptr, evB = nullptr;
    static bool attr_set = false;
    if (!attr_set) {
        cudaStreamCreateWithFlags(&s1, cudaStreamNonBlocking);
        cudaEventCreateWithFlags(&evA, cudaEventDisableTiming);
        cudaEventCreateWithFlags(&evB, cudaEventDisableTiming);
        cudaFuncSetAttribute(k_simsum_mma, cudaFuncAttributeMaxDynamicSharedMemorySize, SIMTC_SMEM);
        cudaFuncSetAttribute(k_mlp, cudaFuncAttributeMaxDynamicSharedMemorySize, MLP_SMEM);
        attr_set = true;
    }

    k_zero<<<(2 * N + 255) / 256, 256>>>();
    k_normalize<<<dim3(N, 3), 128>>>(embF, embM, embP);
    cudaEventRecord(evA, 0);

    // main branch: tensor-core sim sums
    k_simsum_mma<<<dim3(N / 128, JSPLIT), 256, SIMTC_SMEM>>>();

    // side branch: adjacency scan + MLP (DRAM-bound; overlaps tensor work)
    cudaStreamWaitEvent(s1, evA, 0);
    k_repr_pos<<<dim3(N, 2), 128, 0, s1>>>(FM_adj, FP_adj, embM, embP);
    k_mlp<<<N / MLP_ROWS, 256, MLP_SMEM, s1>>>(W1, b1, W2, b2, out + 1);
    cudaEventRecord(evB, s1);

    cudaStreamWaitEvent(0, evB, 0);
    k_loss<<<24, 256>>>();
    k_finalize<<<1, 1>>>(out);
}

// round 14
// speedup vs baseline: 1.9294x; 1.0301x over previous
#include <cuda_runtime.h>
#include <cuda_bf16.h>
#include <math.h>
#include <stdint.h>

#define N 6144
#define D 128
#define INV_TAU 10.0f
#define NB (2 * N)
#define JSPLIT 12
#define TILES_PER 16   // 12*16*64 = 12288 columns

// ---------------- device scratch ----------------
__device__ float g_Fn[N * D];
__device__ float g_Mn[N * D];
__device__ float g_Pn[N * D];
__device__ __nv_bfloat16 g_Abf[N * D];
__device__ __nv_bfloat16 g_Bbf[NB * D];
__device__ float g_repr[2][N * D];
__device__ float g_rowsum[2][N];
__device__ float g_pos[2][N];
__device__ float g_sumall[2][N];
__device__ float g_weights[N * 2];
__device__ float g_loss_acc;

// ---------------- PTX helpers ----------------
__device__ __forceinline__ uint32_t s2u(const void* p) {
    uint32_t a;
    asm("{ .reg .u64 t; cvta.to.shared.u64 t, %1; cvt.u32.u64 %0, t; }" : "=r"(a) : "l"(p));
    return a;
}
__device__ __forceinline__ void cp16(uint32_t dst, const void* src) {
    asm volatile("cp.async.cg.shared.global [%0], [%1], 16;" :: "r"(dst), "l"(src));
}
#define CP_COMMIT() asm volatile("cp.async.commit_group;")
__device__ __forceinline__ void ldsm4(uint32_t* r, uint32_t addr) {
    asm volatile("ldmatrix.sync.aligned.m8n8.x4.shared.b16 {%0,%1,%2,%3}, [%4];"
                 : "=r"(r[0]), "=r"(r[1]), "=r"(r[2]), "=r"(r[3]) : "r"(addr));
}
__device__ __forceinline__ void mma_bf16(float* d, const uint32_t* a, uint32_t b0, uint32_t b1) {
    asm volatile(
        "mma.sync.aligned.m16n8k16.row.col.f32.bf16.bf16.f32 "
        "{%0,%1,%2,%3}, {%4,%5,%6,%7}, {%8,%9}, {%0,%1,%2,%3};"
        : "+f"(d[0]), "+f"(d[1]), "+f"(d[2]), "+f"(d[3])
        : "r"(a[0]), "r"(a[1]), "r"(a[2]), "r"(a[3]), "r"(b0), "r"(b1));
}

// SMEM tiles (stride 272 B = 128 data + 16 pad -> conflict-free ldmatrix)
#define TSTRIDE 272
#define A_TILE_BYTES (128 * TSTRIDE)   // 34816
#define B_TILE_BYTES (64 * TSTRIDE)    // 17408
static constexpr int OFF_A = 0;
static constexpr int OFF_B = A_TILE_BYTES;
static constexpr int SIMTC_SMEM = A_TILE_BYTES + 2 * B_TILE_BYTES;  // 69632

// ---------------- K0: zero ----------------
__global__ void k_zero() {
    int idx = blockIdx.x * blockDim.x + threadIdx.x;
    if (idx < 2 * N) g_sumall[idx / N][idx % N] = 0.0f;
    if (idx == 0) g_loss_acc = 0.0f;
}

// ---------------- K1: normalize + bf16 cast ----------------
__global__ void k_normalize(const float* __restrict__ embF,
                            const float* __restrict__ embM,
                            const float* __restrict__ embP) {
    int i = blockIdx.x;
    int which = blockIdx.y;
    const float* src = (which == 0) ? embF : (which == 1) ? embM : embP;
    float* dst = (which == 0) ? g_Fn : (which == 1) ? g_Mn : g_Pn;
    int t = threadIdx.x;  // 128
    float v = src[(size_t)i * D + t];
    __shared__ float red[128];
    red[t] = v * v;
    __syncthreads();
#pragma unroll
    for (int s = 64; s > 0; s >>= 1) {
        if (t < s) red[t] += red[t + s];
        __syncthreads();
    }
    float norm = fmaxf(sqrtf(red[0]), 1e-12f);
    float nv = v / norm;
    dst[(size_t)i * D + t] = nv;
    __nv_bfloat16 h = __float2bfloat16(nv);
    if (which == 0) g_Abf[i * D + t] = h;
    else g_Bbf[((which == 1) ? i : (N + i)) * D + t] = h;
}

// ---------------- K2: adjacency scan ({0,1} values: integer nonzero test) ----
// rowsum == nonzero count; no value storage, no FP adds on the hot path.
#define MAXNZ 768
__global__ __launch_bounds__(128) void k_repr_pos(
    const float* __restrict__ FM_adj, const float* __restrict__ FP_adj,
    const float* __restrict__ embM, const float* __restrict__ embP) {
    int i = blockIdx.x;
    int w = blockIdx.y;
    const float* adj = (w == 0) ? FM_adj : FP_adj;
    const float* emb = (w == 0) ? embM : embP;
    const float* nrm = (w == 0) ? g_Mn : g_Pn;
    int t = threadIdx.x;
    int lane = t & 31;

    __shared__ int s_idx[MAXNZ];
    __shared__ int s_cnt;
    __shared__ float s_pos;
    __shared__ float s_F[D];

    if (t == 0) { s_cnt = 0; s_pos = 0.0f; }
    s_F[t] = g_Fn[(size_t)i * D + t];
    __syncthreads();

    const uint4* arow = (const uint4*)(adj + (size_t)i * N);
#pragma unroll 4
    for (int c = t; c < N / 4; c += 128) {
        uint4 u = __ldcs(&arow[c]);
        if (((u.x | u.y) | (u.z | u.w)) != 0u) {  // rare (~2%)
            int nh = (u.x != 0u) + (u.y != 0u) + (u.z != 0u) + (u.w != 0u);
            int p = atomicAdd(&s_cnt, nh);
            if (u.x != 0u) { if (p < MAXNZ) s_idx[p] = 4 * c + 0; ++p; }
            if (u.y != 0u) { if (p < MAXNZ) s_idx[p] = 4 * c + 1; ++p; }
            if (u.z != 0u) { if (p < MAXNZ) s_idx[p] = 4 * c + 2; ++p; }
            if (u.w != 0u) { if (p < MAXNZ) s_idx[p] = 4 * c + 3; ++p; }
        }
    }
    __syncthreads();

    int total = s_cnt;
    int cnt = min(total, MAXNZ);
    float denom = fmaxf((float)total, 1.0f);

    // repr gather: thread t = dim, 4 accumulation chains (vals are 1.0)
    float a0 = 0, a1 = 0, a2 = 0, a3 = 0;
    int e = 0;
    for (; e + 4 <= cnt; e += 4) {
        a0 += emb[(size_t)s_idx[e + 0] * D + t];
        a1 += emb[(size_t)s_idx[e + 1] * D + t];
        a2 += emb[(size_t)s_idx[e + 2] * D + t];
        a3 += emb[(size_t)s_idx[e + 3] * D + t];
    }
    for (; e < cnt; ++e) a0 += emb[(size_t)s_idx[e] * D + t];
    g_repr[w][(size_t)i * D + t] = ((a0 + a1) + (a2 + a3)) / denom;
    if (t == 0) g_rowsum[w][i] = (float)total;

    // pos: warp-per-entry dot products (vals are 1.0)
    int warp = t >> 5;
    float lp = 0.0f;
    for (int q = warp; q < cnt; q += 4) {
        int j = s_idx[q];
        const float* nr = nrm + (size_t)j * D;
        float pd = s_F[lane] * nr[lane]
                 + s_F[lane + 32] * nr[lane + 32]
                 + s_F[lane + 64] * nr[lane + 64]
                 + s_F[lane + 96] * nr[lane + 96];
#pragma unroll
        for (int o = 16; o; o >>= 1) pd += __shfl_xor_sync(0xffffffffu, pd, o);
        if (lane == 0) lp += __expf(pd * INV_TAU);
    }
    if (lane == 0) atomicAdd(&s_pos, lp);
    __syncthreads();
    if (t == 0) g_pos[w][i] = s_pos;
}

// ---------------- K3: bf16 HMMA sim row sums (BN=64) ----------------
__device__ __forceinline__ void load_tileA(uint32_t dst, const __nv_bfloat16* src,
                                           int row0, int tid) {
#pragma unroll
    for (int p = 0; p < 8; ++p) {
        int idx = tid + (p << 8);
        int r = idx >> 4, c = idx & 15;
        cp16(dst + r * TSTRIDE + c * 16, src + (size_t)(row0 + r) * D + c * 8);
    }
}
__device__ __forceinline__ void load_tileB(uint32_t dst, const __nv_bfloat16* src,
                                           int row0, int tid) {
#pragma unroll
    for (int p = 0; p < 4; ++p) {
        int idx = tid + (p << 8);
        int r = idx >> 4, c = idx & 15;
        cp16(dst + r * TSTRIDE + c * 16, src + (size_t)(row0 + r) * D + c * 8);
    }
}

__global__ __launch_bounds__(256, 2) void k_simsum_mma() {
    extern __shared__ __align__(16) char dsm[];
    const uint32_t smb = s2u(dsm);
    const int tid = threadIdx.x;
    const int wid = tid >> 5;
    const int lane = tid & 31;
    const int wm = (wid & 3) * 32;
    const int wn = (wid >> 2) * 32;
    const int i0 = blockIdx.x * 128;
    const int tbase = blockIdx.y * TILES_PER;
    const int tgt = (blockIdx.y < JSPLIT / 2) ? 0 : 1;

    const uint32_t aoff = (uint32_t)(lane & 15) * TSTRIDE + (uint32_t)(lane >> 4) * 16;
    const uint32_t boff = (uint32_t)(((lane >> 3) & 1) * 8 + (lane & 7)) * TSTRIDE
                        + (uint32_t)(lane >> 4) * 16;

    load_tileA(smb + OFF_A, g_Abf, i0, tid);
    load_tileB(smb + OFF_B, g_Bbf, tbase * 64, tid);
    CP_COMMIT();
    load_tileB(smb + OFF_B + B_TILE_BYTES, g_Bbf, (tbase + 1) * 64, tid);
    CP_COMMIT();

    float rsum[2][2] = {{0, 0}, {0, 0}};

    for (int t = 0; t < TILES_PER; ++t) {
        const int buf = t & 1;
        asm volatile("cp.async.wait_group 1;");
        __syncthreads();

        const uint32_t bb = smb + OFF_B + buf * B_TILE_BYTES;

        float acc[2][4][4];
#pragma unroll
        for (int f = 0; f < 2; ++f)
#pragma unroll
            for (int n = 0; n < 4; ++n)
#pragma unroll
                for (int r = 0; r < 4; ++r) acc[f][n][r] = 0.0f;

#pragma unroll
        for (int ks = 0; ks < 8; ++ks) {
            uint32_t ah[2][4];
#pragma unroll
            for (int f = 0; f < 2; ++f)
                ldsm4(ah[f], smb + OFF_A + (wm + f * 16) * TSTRIDE + ks * 32 + aoff);
#pragma unroll
            for (int g = 0; g < 2; ++g) {
                uint32_t bh[4];
                ldsm4(bh, bb + (wn + g * 16) * TSTRIDE + ks * 32 + boff);
#pragma unroll
                for (int f = 0; f < 2; ++f) {
                    mma_bf16(acc[f][2 * g], ah[f], bh[0], bh[2]);
                    mma_bf16(acc[f][2 * g + 1], ah[f], bh[1], bh[3]);
                }
            }
        }

        __syncthreads();
        if (t + 2 < TILES_PER)
            load_tileB(smb + OFF_B + buf * B_TILE_BYTES, g_Bbf, (tbase + t + 2) * 64, tid);
        CP_COMMIT();

#pragma unroll
        for (int f = 0; f < 2; ++f) {
            float e0 = 0.0f, e1 = 0.0f;
#pragma unroll
            for (int n = 0; n < 4; ++n) {
                e0 += __expf(acc[f][n][0] * INV_TAU) + __expf(acc[f][n][1] * INV_TAU);
                e1 += __expf(acc[f][n][2] * INV_TAU) + __expf(acc[f][n][3] * INV_TAU);
            }
            rsum[f][0] += e0;
            rsum[f][1] += e1;
        }
    }

#pragma unroll
    for (int f = 0; f < 2; ++f)
#pragma unroll
        for (int r = 0; r < 2; ++r) {
            float v = rsum[f][r];
            v += __shfl_xor_sync(0xffffffffu, v, 1);
            v += __shfl_xor_sync(0xffffffffu, v, 2);
            if ((lane & 3) == 0) {
                int row = i0 + wm + f * 16 + (lane >> 2) + r * 8;
                atomicAdd(&g_sumall[tgt][row], v);
            }
        }
}

// ---------------- K4: MLP + softmax (warp-owned rows) ----------------
#define MLP_ROWS 48
#define FSTR 257
#define MLP_SMEM ((256 * 128 + MLP_ROWS * FSTR) * (int)sizeof(float))
__global__ __launch_bounds__(256) void k_mlp(const float* __restrict__ W1,
                                             const float* __restrict__ b1,
                                             const float* __restrict__ W2,
                                             const float* __restrict__ b2,
                                             float* __restrict__ out_weights) {
    extern __shared__ float smf[];
    float* W1s = smf;
    float* feats = smf + 256 * 128;

    const int tid = threadIdx.x;
    const int lane = tid & 31;
    const int wp = tid >> 5;
    const int i0 = blockIdx.x * MLP_ROWS;

#pragma unroll
    for (int p = 0; p < 32; ++p) {
        int s = tid + p * 256;
        ((float4*)W1s)[s] = ((const float4*)W1)[s];
    }
#pragma unroll
    for (int p = 0; p < MLP_ROWS; ++p) {
        int s = tid + p * 256;
        int r = s >> 8, k = s & 255;
        feats[r * FSTR + k] = (k < 128) ? g_repr[0][(size_t)(i0 + r) * D + k]
                                        : g_repr[1][(size_t)(i0 + r) * D + (k - 128)];
    }
    __syncthreads();

    const int c4 = lane;
    const float4 b1v = ((const float4*)b1)[c4];
    const float4 w2a = ((const float4*)W2)[2 * c4];
    const float4 w2b = ((const float4*)W2)[2 * c4 + 1];
    const int r0 = wp * 6;

    float acc[6][4];
#pragma unroll
    for (int r = 0; r < 6; ++r)
#pragma unroll
        for (int q = 0; q < 4; ++q) acc[r][q] = 0.0f;

#pragma unroll 4
    for (int k = 0; k < 256; ++k) {
        float4 wv = *(const float4*)&W1s[k * 128 + 4 * c4];
#pragma unroll
        for (int r = 0; r < 6; ++r) {
            float f = feats[(r0 + r) * FSTR + k];
            acc[r][0] = fmaf(f, wv.x, acc[r][0]);
            acc[r][1] = fmaf(f, wv.y, acc[r][1]);
            acc[r][2] = fmaf(f, wv.z, acc[r][2]);
            acc[r][3] = fmaf(f, wv.w, acc[r][3]);
        }
    }

#pragma unroll
    for (int r = 0; r < 6; ++r) {
        float h0 = fmaxf(acc[r][0] + b1v.x, 0.0f);
        float h1 = fmaxf(acc[r][1] + b1v.y, 0.0f);
        float h2 = fmaxf(acc[r][2] + b1v.z, 0.0f);
        float h3 = fmaxf(acc[r][3] + b1v.w, 0.0f);
        float p0 = h0 * w2a.x + h1 * w2a.z + h2 * w2b.x + h3 * w2b.z;
        float p1 = h0 * w2a.y + h1 * w2a.w + h2 * w2b.y + h3 * w2b.w;
#pragma unroll
        for (int o = 16; o; o >>= 1) {
            p0 += __shfl_xor_sync(0xffffffffu, p0, o);
            p1 += __shfl_xor_sync(0xffffffffu, p1, o);
        }
        if (lane == 0) {
            int row = i0 + r0 + r;
            float o0 = p0 + b2[0];
            float o1 = p1 + b2[1];
            float mx = fmaxf(o0, o1);
            float e0 = expf(o0 - mx), e1 = expf(o1 - mx);
            float inv = 1.0f / (e0 + e1);
            float w0 = e0 * inv, w1 = e1 * inv;
            g_weights[2 * row] = w0;
            g_weights[2 * row + 1] = w1;
            out_weights[2 * row] = w0;
            out_weights[2 * row + 1] = w1;
        }
    }
}

// ---------------- K5: loss ----------------
__global__ __launch_bounds__(256) void k_loss() {
    int idx = blockIdx.x * blockDim.x + threadIdx.x;
    int stride = gridDim.x * blockDim.x;
    float term = 0.0f;
    for (int i = idx; i < N; i += stride) {
        float w0 = g_weights[2 * i], w1 = g_weights[2 * i + 1];
        float pm = g_pos[0][i], pp = g_pos[1][i];
        float sm = g_sumall[0][i], sp = g_sumall[1][i];
        float wpv = w0 * pm + w1 * pp;
        float wn = w0 * (sm - pm) + w1 * (sp - pp);
        float nei = fmaxf(g_rowsum[0][i] + g_rowsum[1][i], 1.0f);
        float ratio = wpv / (wpv + wn) / nei;
        ratio = fmaxf(ratio, 1e-10f);
        term += -logf(ratio);
    }
    __shared__ float red[256];
    red[threadIdx.x] = term;
    __syncthreads();
#pragma unroll
    for (int s = 128; s > 0; s >>= 1) {
        if (threadIdx.x < s) red[threadIdx.x] += red[threadIdx.x + s];
        __syncthreads();
    }
    if (threadIdx.x == 0) atomicAdd(&g_loss_acc, red[0]);
}

__global__ void k_finalize(float* __restrict__ out) {
    out[0] = g_loss_acc / (float)N;
}

// ---------------- launch (fork-join overlap; side stream = high priority) ----
extern "C" void kernel_launch(void* const* d_in, const int* in_sizes, int n_in,
                              void* d_out, int out_size) {
    const float* embF = (const float*)d_in[0];
    const float* embM = (const float*)d_in[1];
    const float* embP = (const float*)d_in[2];
    const float* FM_adj = (const float*)d_in[3];
    const float* FP_adj = (const float*)d_in[4];
    const float* W1 = (const float*)d_in[5];
    const float* b1 = (const float*)d_in[6];
    const float* W2 = (const float*)d_in[7];
    const float* b2 = (const float*)d_in[8];
    float* out = (float*)d_out;

    static cudaStream_t s1 = nullptr;
    static cudaEvent_t evA = nullptr, evB = nullptr;
    static bool attr_set = false;
    if (!attr_set) {
        int lo, hi;
        cudaDeviceGetStreamPriorityRange(&lo, &hi);
        cudaStreamCreateWithPriority(&s1, cudaStreamNonBlocking, hi);
        cudaEventCreateWithFlags(&evA, cudaEventDisableTiming);
        cudaEventCreateWithFlags(&evB, cudaEventDisableTiming);
        cudaFuncSetAttribute(k_simsum_mma, cudaFuncAttributeMaxDynamicSharedMemorySize, SIMTC_SMEM);
        cudaFuncSetAttribute(k_mlp, cudaFuncAttributeMaxDynamicSharedMemorySize, MLP_SMEM);
        attr_set = true;
    }

    k_zero<<<(2 * N + 255) / 256, 256>>>();
    k_normalize<<<dim3(N, 3), 128>>>(embF, embM, embP);
    cudaEventRecord(evA, 0);

    // main branch: tensor-core sim sums
    k_simsum_mma<<<dim3(N / 128, JSPLIT), 256, SIMTC_SMEM>>>();

    // side branch (critical path): adjacency scan + MLP on high-priority stream
    cudaStreamWaitEvent(s1, evA, 0);
    k_repr_pos<<<dim3(N, 2), 128, 0, s1>>>(FM_adj, FP_adj, embM, embP);
    k_mlp<<<N / MLP_ROWS, 256, MLP_SMEM, s1>>>(W1, b1, W2, b2, out + 1);
    cudaEventRecord(evB, s1);

    cudaStreamWaitEvent(0, evB, 0);
    k_loss<<<24, 256>>>();
    k_finalize<<<1, 1>>>(out);
}